// round 1
// baseline (speedup 1.0000x reference)
#include <cuda_runtime.h>

#define NEG_INF __int_as_float(0xff800000)

// out[b,o,y,x] = max_{c,dy,dx} img[b,c,y+dy-1,x+dx-1] + ker[o,c,2-dy,2-dx]
// B=8, C=32, H=W=32, O=32, 3x3, pad=1 (-inf), OY=OX=32
//
// Grid: 256 blocks = 8 batches x 8 o-groups(4 o) x 4 row-strips(8 rows)
// Block: 128 threads = 4 warps; warp w owns o_local=w; lane: y=lane>>2, xg=lane&3
// Each thread computes 8 consecutive x pixels of one output row for one o.
__global__ __launch_bounds__(128) void bconv_kernel(
    const float* __restrict__ img,   // [8][32][32][32]
    const float* __restrict__ ker,   // [32][32][3][3]
    float* __restrict__ out)         // [8][32][32][32]
{
    // stride 33 -> window LDS bank = (y + 8*xg + const) % 32 : conflict-free
    __shared__ float tile[32][10][33];   // 42240 B  (col s stores actual col s-1; s=0 is -inf halo)
    __shared__ float ksm[32][9][4];      //  4608 B  ksm[c][t][ol] = ker[o][c][8-t]

    const int bx  = blockIdx.x;
    const int b   = bx >> 5;         // 0..7
    const int og  = (bx >> 2) & 7;   // 0..7  (4 o's each)
    const int ys  = bx & 3;          // 0..3  (8 rows each)
    const int y0  = ys << 3;
    const int tid = threadIdx.x;

    // ---- reformat kernel (flip) into smem, o-contiguous for broadcast reads ----
    for (int i = tid; i < 32 * 9 * 4; i += 128) {
        int ol = i & 3;
        int ct = i >> 2;
        int c  = ct / 9;
        int t  = ct - c * 9;
        ksm[c][t][ol] = ker[((og * 4 + ol) * 32 + c) * 9 + (8 - t)];
    }

    // ---- stage image strip (rows y0-1 .. y0+8) for all 32 channels ----
    const float* imb = img + (b << 15);   // b*32*32*32
    for (int i = tid; i < 10 * 32 * 32; i += 128) {   // all power-of-2 index math
        int r  = i >> 10;          // padded row 0..9
        int c  = (i >> 5) & 31;    // channel
        int cc = i & 31;           // actual col
        int gy = y0 + r - 1;
        float v = NEG_INF;
        if ((unsigned)gy < 32u)
            v = imb[(c << 10) + (gy << 5) + cc];
        tile[c][r][cc + 1] = v;
    }
    // left halo (actual col -1): always out of image -> -inf
    for (int h = tid; h < 32 * 10; h += 128) {
        int c = h / 10;
        int r = h - c * 10;
        tile[c][r][0] = NEG_INF;
    }
    __syncthreads();

    const int  w    = tid >> 5;      // o_local (warp-uniform)
    const int  lane = tid & 31;
    const int  y    = lane >> 2;     // local output row 0..7
    const int  xg   = lane & 3;      // pixel group
    const int  xb   = xg << 3;       // first pixel x
    const bool rgt  = (xg == 3);
    const int  s9   = rgt ? 32 : xb + 9;   // clamped smem col for j=9

    float acc[8];
    #pragma unroll
    for (int p = 0; p < 8; p++) acc[p] = NEG_INF;

    for (int c = 0; c < 32; c++) {
        // window: padded cols xb .. xb+9 (= actual cols xb-1 .. xb+8), rows y..y+2
        float win[3][10];
        #pragma unroll
        for (int dy = 0; dy < 3; dy++) {
            const float* rowp = &tile[c][y + dy][0];
            #pragma unroll
            for (int j = 0; j < 9; j++)
                win[dy][j] = rowp[xb + j];
            float v = rowp[s9];                 // in-bounds clamped read
            win[dy][9] = rgt ? NEG_INF : v;     // actual col 32 -> -inf
        }
        float kv[9];
        #pragma unroll
        for (int t = 0; t < 9; t++) kv[t] = ksm[c][t][w];   // broadcast LDS

        #pragma unroll
        for (int t = 0; t < 9; t++) {
            const int dy = t / 3, dx = t % 3;   // constants after unroll
            const float k = kv[t];
            #pragma unroll
            for (int p = 0; p < 8; p++)
                acc[p] = fmaxf(acc[p], win[dy][dx + p] + k);
        }
    }

    const int o = (og << 2) + w;
    float* op = out + (((b << 5) + o) << 10) + ((y0 + y) << 5) + xb;
    reinterpret_cast<float4*>(op)[0] = make_float4(acc[0], acc[1], acc[2], acc[3]);
    reinterpret_cast<float4*>(op)[1] = make_float4(acc[4], acc[5], acc[6], acc[7]);
}

extern "C" void kernel_launch(void* const* d_in, const int* in_sizes, int n_in,
                              void* d_out, int out_size) {
    const float* img = (const float*)d_in[0];   // 262144 floats
    const float* ker = (const float*)d_in[1];   // 9216 floats
    float* outp = (float*)d_out;                // 262144 floats
    bconv_kernel<<<256, 128>>>(img, ker, outp);
}

// round 5
// speedup vs baseline: 1.2739x; 1.2739x over previous
#include <cuda_runtime.h>

#define NEG_INF __int_as_float(0xff800000)

// Tropical conv: out[b,o,y,x] = max_{c,dy,dx} img[b,c,y+dy-1,x+dx-1] + ker[o,c,2-dy,2-dx]
// B=8, C=32, H=W=32, O=32, 3x3, pad=1 (-inf)
//
// Grid: 512 blocks = 8 batches x 16 o-groups(2 o) x 4 row-strips(8 rows)
// Block: 256 threads = 8 warps = 2 o_local x 4 c-groups (8 channels each).
// Lane: y = lane>>2 (8 rows), xg = lane&3 (4 pixel-groups of 8).
// Each thread computes 8 consecutive x pixels for (o, row, c-range); the 4
// c-group partials are max-combined through smem (overlaid on the dead tile).
__global__ __launch_bounds__(256) void bconv_kernel(
    const float* __restrict__ img,   // [8][32][32][32]
    const float* __restrict__ ker,   // [32][32][3][3]
    float* __restrict__ out)         // [8][32][32][32]
{
    // stride 33 -> window LDS bank = (y + 8*xg + const) % 32 : conflict-free
    __shared__ float tile[32][10][33];   // 42240 B ; col s = actual col s-1; s=0 is -inf halo
    __shared__ float ksm[32][9][2];      //  2304 B ; ksm[c][t][ol] = ker[o][c][8-t]
    // partial buffer overlaid on tile after mainloop: [3][2][32][9] floats (6912 B)
    float* part = &tile[0][0][0];

    const int bx  = blockIdx.x;
    const int b   = bx >> 6;          // 0..7
    const int og  = (bx >> 2) & 15;   // 0..15  (2 o's each)
    const int ys  = bx & 3;           // 0..3   (8 rows each)
    const int y0  = ys << 3;
    const int tid = threadIdx.x;

    // ---- reformat flipped kernel into smem, o-contiguous for broadcast reads ----
    for (int i = tid; i < 32 * 9 * 2; i += 256) {
        int ol = i & 1;
        int ct = i >> 1;
        int c  = ct / 9;
        int t  = ct - c * 9;
        ksm[c][t][ol] = ker[((og * 2 + ol) * 32 + c) * 9 + (8 - t)];
    }

    // ---- stage image strip (rows y0-1 .. y0+8) for all 32 channels ----
    const float* imb = img + (b << 15);
    for (int i = tid; i < 10 * 32 * 32; i += 256) {
        int r  = i >> 10;          // padded row 0..9
        int c  = (i >> 5) & 31;    // channel
        int cc = i & 31;           // actual col
        int gy = y0 + r - 1;
        float v = NEG_INF;
        if ((unsigned)gy < 32u)
            v = imb[(c << 10) + (gy << 5) + cc];
        tile[c][r][cc + 1] = v;
    }
    for (int h = tid; h < 32 * 10; h += 256) {   // left halo col (-1): -inf
        int c = h / 10;
        int r = h - c * 10;
        tile[c][r][0] = NEG_INF;
    }
    __syncthreads();

    const int  wid  = tid >> 5;
    const int  ol   = wid & 1;       // o_local (warp-uniform)
    const int  g    = wid >> 1;      // c-group 0..3 (warp-uniform)
    const int  lane = tid & 31;
    const int  y    = lane >> 2;     // local output row 0..7
    const int  xg   = lane & 3;      // pixel group
    const int  xb   = xg << 3;       // first pixel x
    const bool rgt  = (xg == 3);
    const int  s9   = rgt ? 32 : xb + 9;   // clamped smem col for j=9

    float acc[8];
    #pragma unroll
    for (int p = 0; p < 8; p++) acc[p] = NEG_INF;

    const int c0 = g << 3;
    #pragma unroll 2
    for (int ci = 0; ci < 8; ci++) {
        const int c = c0 + ci;
        // window: padded cols xb..xb+9 (= actual xb-1..xb+8), rows y..y+2
        float win[3][10];
        #pragma unroll
        for (int dy = 0; dy < 3; dy++) {
            const float* rowp = &tile[c][y + dy][0];
            #pragma unroll
            for (int j = 0; j < 9; j++)
                win[dy][j] = rowp[xb + j];
            float v = rowp[s9];                 // in-bounds clamped read
            win[dy][9] = rgt ? NEG_INF : v;     // actual col 32 -> -inf
        }
        float kv[9];
        #pragma unroll
        for (int t = 0; t < 9; t++) kv[t] = ksm[c][t][ol];  // broadcast LDS

        #pragma unroll
        for (int t = 0; t < 9; t++) {
            const int dy = t / 3, dx = t % 3;
            const float k = kv[t];
            #pragma unroll
            for (int p = 0; p < 8; p++)
                acc[p] = fmaxf(acc[p], win[dy][dx + p] + k);
        }
    }

    // ---- combine the 4 c-group partials (overlay buffer on dead tile) ----
    __syncthreads();   // everyone done reading tile
    if (g > 0) {
        float* dst = part + (((g - 1) * 2 + ol) * 32 + lane) * 9;  // stride 9: conflict-free
        #pragma unroll
        for (int p = 0; p < 8; p++) dst[p] = acc[p];
    }
    __syncthreads();
    if (g == 0) {
        #pragma unroll
        for (int gg = 0; gg < 3; gg++) {
            const float* src = part + ((gg * 2 + ol) * 32 + lane) * 9;
            #pragma unroll
            for (int p = 0; p < 8; p++)
                acc[p] = fmaxf(acc[p], src[p]);
        }
        const int o = (og << 1) + ol;
        float* op = out + (((b << 5) + o) << 10) + ((y0 + y) << 5) + xb;
        reinterpret_cast<float4*>(op)[0] = make_float4(acc[0], acc[1], acc[2], acc[3]);
        reinterpret_cast<float4*>(op)[1] = make_float4(acc[4], acc[5], acc[6], acc[7]);
    }
}

extern "C" void kernel_launch(void* const* d_in, const int* in_sizes, int n_in,
                              void* d_out, int out_size) {
    const float* img = (const float*)d_in[0];
    const float* ker = (const float*)d_in[1];
    float* outp = (float*)d_out;
    bconv_kernel<<<512, 256>>>(img, ker, outp);
}